// round 8
// baseline (speedup 1.0000x reference)
#include <cuda_runtime.h>
#include <cstdint>

#define MM 512
#define NN 1024
#define WR 16
#define BB 4096

#define ABSM 0x7FFFFFFFu
#define SGNM 0x80000000u

// Per-lane c2v: g_c2v[(cn*BB + batch)*4 + q] = float4 (edges 4q..4q+3). 128 MB.
__device__ float4 g_c2v[MM * BB * 4];

extern __shared__ float sh_vn[];        // [NN][32] floats = 128 KB

// Prefetch slot S for global step T (first pass over each cn -> c2v_old = 0).
#define PREFETCH(S, T) do {                                                  \
    cn##S = __ldg(&cn_order[tm]); if (++tm == MM) tm = 0;                    \
    const int4* hp_ = (const int4*)H + cn##S * 4;                            \
    i0##S = __ldg(hp_ + 0); i1##S = __ldg(hp_ + 1);                          \
    i2##S = __ldg(hp_ + 2); i3##S = __ldg(hp_ + 3);                          \
    const float4* cp_ = g_c2v + (cn##S * BB + gb) * 4;                       \
    c0##S = cp_[0]; c1##S = cp_[1]; c2##S = cp_[2]; c3##S = cp_[3];          \
    if ((T) < MM) { c0##S = f4z; c1##S = f4z; c2##S = f4z; c3##S = f4z; }    \
} while (0)

// One edge input: v2c and |v2c|
#define E(v2, ab, idx, co)                                                   \
    const float v2 = vnl[(idx) << 5] - (co);                                 \
    const float ab = __uint_as_float(__float_as_uint(v2) & ABSM);

// One edge output: new c2v value + vn update
#define O(cv, v2, ab, idx)                                                   \
    const float amp_##cv = (ab == m1) ? m2c : m1c;                           \
    const float cv = __uint_as_float(__float_as_uint(amp_##cv) |             \
                     ((par ^ __float_as_uint(v2)) & SGNM));                  \
    vnl[(idx) << 5] = v2 + cv;

// Full check-node update for slot S: all 16 edges in-thread, no cross-lane ops.
#define STEP(S) do {                                                         \
    E(t00, a00, i0##S.x, c0##S.x) E(t01, a01, i0##S.y, c0##S.y)              \
    E(t02, a02, i0##S.z, c0##S.z) E(t03, a03, i0##S.w, c0##S.w)              \
    E(t04, a04, i1##S.x, c1##S.x) E(t05, a05, i1##S.y, c1##S.y)              \
    E(t06, a06, i1##S.z, c1##S.z) E(t07, a07, i1##S.w, c1##S.w)              \
    E(t08, a08, i2##S.x, c2##S.x) E(t09, a09, i2##S.y, c2##S.y)              \
    E(t10, a10, i2##S.z, c2##S.z) E(t11, a11, i2##S.w, c2##S.w)              \
    E(t12, a12, i3##S.x, c3##S.x) E(t13, a13, i3##S.y, c3##S.y)              \
    E(t14, a14, i3##S.z, c3##S.z) E(t15, a15, i3##S.w, c3##S.w)              \
    /* (min1,min2) tree over the 16 |v2c| */                                 \
    const float n0 = fminf(a00,a01), x0 = fmaxf(a00,a01);                    \
    const float n1 = fminf(a02,a03), x1 = fmaxf(a02,a03);                    \
    const float n2 = fminf(a04,a05), x2 = fmaxf(a04,a05);                    \
    const float n3 = fminf(a06,a07), x3 = fmaxf(a06,a07);                    \
    const float n4 = fminf(a08,a09), x4 = fmaxf(a08,a09);                    \
    const float n5 = fminf(a10,a11), x5 = fmaxf(a10,a11);                    \
    const float n6 = fminf(a12,a13), x6 = fmaxf(a12,a13);                    \
    const float n7 = fminf(a14,a15), x7 = fmaxf(a14,a15);                    \
    const float e0a = fminf(n0,n1), e0b = fminf(fmaxf(n0,n1), fminf(x0,x1)); \
    const float e1a = fminf(n2,n3), e1b = fminf(fmaxf(n2,n3), fminf(x2,x3)); \
    const float e2a = fminf(n4,n5), e2b = fminf(fmaxf(n4,n5), fminf(x4,x5)); \
    const float e3a = fminf(n6,n7), e3b = fminf(fmaxf(n6,n7), fminf(x6,x7)); \
    const float f0a = fminf(e0a,e1a);                                        \
    const float f0b = fminf(fmaxf(e0a,e1a), fminf(e0b,e1b));                 \
    const float f1a = fminf(e2a,e3a);                                        \
    const float f1b = fminf(fmaxf(e2a,e3a), fminf(e2b,e3b));                 \
    const float m1  = fminf(f0a,f1a);                                        \
    const float m2  = fminf(fmaxf(f0a,f1a), fminf(f0b,f1b));                 \
    /* sign parity over all 16 edges */                                      \
    unsigned par = (__float_as_uint(t00)^__float_as_uint(t01))               \
                 ^ (__float_as_uint(t02)^__float_as_uint(t03))               \
                 ^ (__float_as_uint(t04)^__float_as_uint(t05))               \
                 ^ (__float_as_uint(t06)^__float_as_uint(t07))               \
                 ^ (__float_as_uint(t08)^__float_as_uint(t09))               \
                 ^ (__float_as_uint(t10)^__float_as_uint(t11))               \
                 ^ (__float_as_uint(t12)^__float_as_uint(t13))               \
                 ^ (__float_as_uint(t14)^__float_as_uint(t15));              \
    par &= SGNM;                                                             \
    const float m1c = fminf(m1, 20.0f);                                      \
    const float m2c = fminf(m2, 20.0f);                                      \
    O(w00, t00, a00, i0##S.x) O(w01, t01, a01, i0##S.y)                      \
    O(w02, t02, a02, i0##S.z) O(w03, t03, a03, i0##S.w)                      \
    O(w04, t04, a04, i1##S.x) O(w05, t05, a05, i1##S.y)                      \
    O(w06, t06, a06, i1##S.z) O(w07, t07, a07, i1##S.w)                      \
    O(w08, t08, a08, i2##S.x) O(w09, t09, a09, i2##S.y)                      \
    O(w10, t10, a10, i2##S.z) O(w11, t11, a11, i2##S.w)                      \
    O(w12, t12, a12, i3##S.x) O(w13, t13, a13, i3##S.y)                      \
    O(w14, t14, a14, i3##S.z) O(w15, t15, a15, i3##S.w)                      \
    float4* wp_ = g_c2v + (cn##S * BB + gb) * 4;                             \
    wp_[0] = make_float4(w00, w01, w02, w03);                                \
    wp_[1] = make_float4(w04, w05, w06, w07);                                \
    wp_[2] = make_float4(w08, w09, w10, w11);                                \
    wp_[3] = make_float4(w12, w13, w14, w15);                                \
} while (0)

__global__ __launch_bounds__(32)
void ldpc_layered_ms_kernel(const float* __restrict__ llr,
                            const int*   __restrict__ H,
                            const int*   __restrict__ iters_p,
                            const int*   __restrict__ cn_order,
                            float*       __restrict__ out)
{
    const int lane = threadIdx.x;                // lane == local batch
    const int gb   = blockIdx.x * 32 + lane;     // global batch
    float* vnl = sh_vn + lane;                   // private smem column (bank==lane)
    const float4 f4z = make_float4(0.f, 0.f, 0.f, 0.f);

    // Load channel LLRs into transposed smem (STS all conflict-free: bank == lane).
    const float4* src = (const float4*)(llr + (size_t)gb * NN);
    #pragma unroll 4
    for (int k = 0; k < NN / 4; ++k) {
        const float4 v = __ldg(src + k);
        vnl[(4*k + 0) << 5] = v.x;
        vnl[(4*k + 1) << 5] = v.y;
        vnl[(4*k + 2) << 5] = v.z;
        vnl[(4*k + 3) << 5] = v.w;
    }

    const int iters = *iters_p;
    const int total = iters * MM;               // 2560, even

    int  cnA, cnB;
    int4 i0A,i1A,i2A,i3A, i0B,i1B,i2B,i3B;
    float4 c0A,c1A,c2A,c3A, c0B,c1B,c2B,c3B;
    int tm = 0, tp = 8;
    PREFETCH(A, 0);
    PREFETCH(B, 1);

    for (int t = 0; t < total; t += 2) {
        // L2 warm for steps t+8 / t+9 (non-binding; distinct cn from pending stores)
        {
            const int cnp = __ldg(&cn_order[tp]); if (++tp == MM) tp = 0;
            const float4* pp = g_c2v + (cnp * BB + gb) * 4;
            asm volatile("prefetch.global.L2 [%0];" :: "l"(pp));
            const int cnq = __ldg(&cn_order[tp]); if (++tp == MM) tp = 0;
            const float4* qq = g_c2v + (cnq * BB + gb) * 4;
            asm volatile("prefetch.global.L2 [%0];" :: "l"(qq));
        }
        STEP(A); PREFETCH(A, t + 2);
        STEP(B); PREFETCH(B, t + 3);
    }

    // Hard decision (LDS conflict-free; stores 16B/lane).
    float4* dst = (float4*)(out + (size_t)gb * NN);
    #pragma unroll 4
    for (int k = 0; k < NN / 4; ++k) {
        float4 r;
        r.x = (vnl[(4*k + 0) << 5] < 0.f) ? 1.f : 0.f;
        r.y = (vnl[(4*k + 1) << 5] < 0.f) ? 1.f : 0.f;
        r.z = (vnl[(4*k + 2) << 5] < 0.f) ? 1.f : 0.f;
        r.w = (vnl[(4*k + 3) << 5] < 0.f) ? 1.f : 0.f;
        dst[k] = r;
    }
}

extern "C" void kernel_launch(void* const* d_in, const int* in_sizes, int n_in,
                              void* d_out, int out_size)
{
    const float* llr      = (const float*)d_in[0];   // channel_llr [4096,1024] f32
    const int*   H        = (const int*)  d_in[1];   // H_compact   [512,16]    i32
    const int*   iters_p  = (const int*)  d_in[2];   // iters scalar
    const int*   cn_order = (const int*)  d_in[3];   // cn_order    [512]       i32
    float*       out      = (float*)d_out;

    (void)in_sizes; (void)n_in; (void)out_size;

    const int smem = NN * 32 * (int)sizeof(float);   // 128 KB dynamic
    cudaFuncSetAttribute(ldpc_layered_ms_kernel,
                         cudaFuncAttributeMaxDynamicSharedMemorySize, smem);
    ldpc_layered_ms_kernel<<<BB / 32, 32, smem>>>(llr, H, iters_p, cn_order, out);
}

// round 9
// speedup vs baseline: 1.7045x; 1.7045x over previous
#include <cuda_runtime.h>
#include <cstdint>

#define MM 512
#define NN 1024
#define WR 16
#define BB 4096
#define G  8            // batch elements per block (16 lanes each -> 128 threads)
#define STRIDE 1032     // padded floats per batch row in smem

#define ABSM 0x7FFFFFFFu
#define SGNM 0x80000000u
#define FULL 0xFFFFFFFFu

// Compressed c2v per (cn, batch): {m1c bits, m2c bits, flips|am<<16, pad} = 16 B.
// flips_i = sign(cnew_i); amp_i = (i==am) ? m2c : m1c.  32 MB -> L2-resident.
__device__ uint4 g_c2v[MM * BB];

// Prefetch slot S for global step T. Unpacks per-lane c2v_old off the chain.
#define PREFETCH(S, T) do {                                                  \
    cn##S  = __ldg(&cn_order[tm]); if (++tm == MM) tm = 0;                   \
    idx##S = __ldg(&H[cn##S * WR + i]);                                      \
    if ((T) < MM) {                                                          \
        co##S = 0.0f;                                                        \
    } else {                                                                 \
        const uint4 cc = g_c2v[cn##S * BB + batch];                          \
        const unsigned amp = (i == (int)((cc.z >> 16) & 31u)) ? cc.y : cc.x; \
        co##S = __uint_as_float(amp | ((cc.z << (31 - i)) & SGNM));          \
    }                                                                        \
} while (0)

// One check-node update: 1 edge/lane, 4-stage full-mask butterfly over 16 lanes.
#define STEP(S) do {                                                         \
    const float v2c = vn[idx##S] - co##S;                                    \
    const unsigned vb = __float_as_uint(v2c);                                \
    const float ab = __uint_as_float(vb & ABSM);                             \
    const unsigned bal = __ballot_sync(FULL, vb >= SGNM);   /* sign bits */  \
    float m1 = ab, m2;                                                       \
    {   const float o = __shfl_xor_sync(FULL, m1, 1);                        \
        m2 = fmaxf(m1, o); m1 = fminf(m1, o); }                              \
    {   const float o1 = __shfl_xor_sync(FULL, m1, 2);                       \
        const float o2 = __shfl_xor_sync(FULL, m2, 2);                       \
        m2 = fminf(fmaxf(m1, o1), fminf(m2, o2)); m1 = fminf(m1, o1); }      \
    {   const float o1 = __shfl_xor_sync(FULL, m1, 4);                       \
        const float o2 = __shfl_xor_sync(FULL, m2, 4);                       \
        m2 = fminf(fmaxf(m1, o1), fminf(m2, o2)); m1 = fminf(m1, o1); }      \
    {   const float o1 = __shfl_xor_sync(FULL, m1, 8);                       \
        const float o2 = __shfl_xor_sync(FULL, m2, 8);                       \
        m2 = fminf(fmaxf(m1, o1), fminf(m2, o2)); m1 = fminf(m1, o1); }      \
    const unsigned eq  = __ballot_sync(FULL, ab == m1);                      \
    const int am       = __ffs((eq >> gbase) & 0xFFFFu) - 1;                 \
    const unsigned signs = (bal >> gbase) & 0xFFFFu;                         \
    const unsigned pbit  = (unsigned)__popc(signs) & 1u;                     \
    const float m1c = fminf(m1, 20.0f);                                      \
    const float m2c = fminf(m2, 20.0f);                                      \
    const float ampf = (i == am) ? m2c : m1c;                                \
    const unsigned sgn = ((pbit << 31) ^ vb) & SGNM;                         \
    const float cnew = __uint_as_float(__float_as_uint(ampf) | sgn);         \
    vn[idx##S] = v2c + cnew;                                                 \
    if (i == 0) {                                                            \
        uint4 nc;                                                            \
        nc.x = __float_as_uint(m1c);                                         \
        nc.y = __float_as_uint(m2c);                                         \
        nc.z = ((signs ^ ((0u - pbit) & 0xFFFFu)) & 0xFFFFu)                 \
             | ((unsigned)am << 16);                                         \
        nc.w = 0u;                                                           \
        g_c2v[cn##S * BB + batch] = nc;                                      \
    }                                                                        \
    __syncwarp();                                                            \
} while (0)

__global__ __launch_bounds__(G * 16)
void ldpc_layered_ms_kernel(const float* __restrict__ llr,
                            const int*   __restrict__ H,
                            const int*   __restrict__ iters_p,
                            const int*   __restrict__ cn_order,
                            float*       __restrict__ out)
{
    __shared__ float sh_vn[G * STRIDE];

    const int tid   = threadIdx.x;
    const int lane  = tid & 31;
    const int i     = tid & 15;                 // edge index within row
    const int g     = tid >> 4;                 // local batch index
    const int batch = blockIdx.x * G + g;
    const int gbase = lane & 16;                // 0 low half, 16 high half

    float* vn = sh_vn + g * STRIDE;

    #pragma unroll 4
    for (int n = i; n < NN; n += 16)
        vn[n] = llr[batch * NN + n];
    __syncwarp();

    const int iters = *iters_p;
    const int total = iters * MM;               // 2560, even

    // ---- 2-deep software pipeline ----
    int cnA, cnB, idxA, idxB;
    float coA, coB;
    int tm = 0;
    PREFETCH(A, 0);
    PREFETCH(B, 1);

    for (int t = 0; t < total; t += 2) {
        STEP(A); PREFETCH(A, t + 2);   // cn_{t+2} != cn_t: safe vs this step's store
        STEP(B); PREFETCH(B, t + 3);
    }

    // Hard decision output.
    #pragma unroll 4
    for (int n = i; n < NN; n += 16)
        out[batch * NN + n] = (vn[n] < 0.0f) ? 1.0f : 0.0f;
}

extern "C" void kernel_launch(void* const* d_in, const int* in_sizes, int n_in,
                              void* d_out, int out_size)
{
    const float* llr      = (const float*)d_in[0];   // channel_llr [4096,1024] f32
    const int*   H        = (const int*)  d_in[1];   // H_compact   [512,16]    i32
    const int*   iters_p  = (const int*)  d_in[2];   // iters scalar
    const int*   cn_order = (const int*)  d_in[3];   // cn_order    [512]       i32
    float*       out      = (float*)d_out;

    (void)in_sizes; (void)n_in; (void)out_size;

    ldpc_layered_ms_kernel<<<BB / G, G * 16>>>(llr, H, iters_p, cn_order, out);
}

// round 10
// speedup vs baseline: 2.0980x; 1.2309x over previous
#include <cuda_runtime.h>
#include <cstdint>

#define MM 512
#define NN 1024
#define WR 16
#define BB 4096
#define BPB 8            // batches per block (2 warps, 8 lanes per batch)
#define STRIDE 1028      // padded floats per batch row in smem

#define ABSM 0x7FFFFFFFu
#define SGNM 0x80000000u
#define FULL 0xFFFFFFFFu

// Compressed c2v per (cn, batch): {m1c, m2c, flips16|eq16<<16, pad} = 16 B.
// Edge b (= li + 8*e): amp = (eq>>b)&1 ? m2c : m1c; sign = (flips>>b)&1.
// 32 MB total -> fully L2-resident.
__device__ uint4 g_c2v[MM * BB];

// Prefetch slot S for global step T. Unpacks this lane's two edges off-chain.
#define PREFETCH(S, T) do {                                                  \
    cn##S  = __ldg(&cn_order[tm]); if (++tm == MM) tm = 0;                   \
    ilo##S = __ldg(&H[cn##S * WR + li]);                                     \
    ihi##S = __ldg(&H[cn##S * WR + li + 8]);                                 \
    if ((T) < MM) {                                                          \
        clo##S = 0.0f; chi##S = 0.0f;                                        \
    } else {                                                                 \
        const uint4 cc = g_c2v[cn##S * BB + batch];                          \
        const unsigned alo_ = ((cc.z >> (16 + li)) & 1u) ? cc.y : cc.x;      \
        const unsigned ahi_ = ((cc.z >> (24 + li)) & 1u) ? cc.y : cc.x;      \
        clo##S = __uint_as_float(alo_ | ((cc.z << (31 - li)) & SGNM));       \
        chi##S = __uint_as_float(ahi_ | ((cc.z << (23 - li)) & SGNM));       \
    }                                                                        \
} while (0)

// One check-node update: 2 edges/lane, 3-stage full-mask butterfly over 8 lanes.
#define STEP(S) do {                                                         \
    const float tlo = vn[ilo##S] - clo##S;                                   \
    const float thi = vn[ihi##S] - chi##S;                                   \
    const unsigned ulo = __float_as_uint(tlo);                               \
    const unsigned uhi = __float_as_uint(thi);                               \
    const float alo = __uint_as_float(ulo & ABSM);                           \
    const float ahi = __uint_as_float(uhi & ABSM);                           \
    const unsigned blo = __ballot_sync(FULL, ulo >= SGNM);                   \
    const unsigned bhi = __ballot_sync(FULL, uhi >= SGNM);                   \
    float m1 = fminf(alo, ahi);                                              \
    float m2 = fmaxf(alo, ahi);                                              \
    {   const float o1 = __shfl_xor_sync(FULL, m1, 1);                       \
        const float o2 = __shfl_xor_sync(FULL, m2, 1);                       \
        m2 = fminf(fmaxf(m1, o1), fminf(m2, o2)); m1 = fminf(m1, o1); }      \
    {   const float o1 = __shfl_xor_sync(FULL, m1, 2);                       \
        const float o2 = __shfl_xor_sync(FULL, m2, 2);                       \
        m2 = fminf(fmaxf(m1, o1), fminf(m2, o2)); m1 = fminf(m1, o1); }      \
    {   const float o1 = __shfl_xor_sync(FULL, m1, 4);                       \
        const float o2 = __shfl_xor_sync(FULL, m2, 4);                       \
        m2 = fminf(fmaxf(m1, o1), fminf(m2, o2)); m1 = fminf(m1, o1); }      \
    const unsigned elo = __ballot_sync(FULL, alo == m1);                     \
    const unsigned ehi = __ballot_sync(FULL, ahi == m1);                     \
    const float m1c = fminf(m1, 20.0f);                                      \
    const float m2c = fminf(m2, 20.0f);                                      \
    const unsigned s16 = ((blo >> sh) & 0xFFu) | (((bhi >> sh) & 0xFFu) << 8); \
    const unsigned par = (unsigned)__popc(s16) & 1u;                         \
    const unsigned par31 = par << 31;                                        \
    const float amplo = (alo == m1) ? m2c : m1c;                             \
    const float amphi = (ahi == m1) ? m2c : m1c;                             \
    const float cwlo = __uint_as_float(__float_as_uint(amplo)                \
                                       | ((par31 ^ ulo) & SGNM));            \
    const float cwhi = __uint_as_float(__float_as_uint(amphi)                \
                                       | ((par31 ^ uhi) & SGNM));            \
    vn[ilo##S] = tlo + cwlo;                                                 \
    vn[ihi##S] = thi + cwhi;                                                 \
    if (li == 0) {                                                           \
        const unsigned e16 = ((elo >> sh) & 0xFFu)                           \
                           | (((ehi >> sh) & 0xFFu) << 8);                   \
        uint4 nc;                                                            \
        nc.x = __float_as_uint(m1c);                                         \
        nc.y = __float_as_uint(m2c);                                         \
        nc.z = (s16 ^ ((0u - par) & 0xFFFFu)) | (e16 << 16);                 \
        nc.w = 0u;                                                           \
        g_c2v[cn##S * BB + batch] = nc;                                      \
    }                                                                        \
    __syncwarp();                                                            \
} while (0)

__global__ __launch_bounds__(64)
void ldpc_layered_ms_kernel(const float* __restrict__ llr,
                            const int*   __restrict__ H,
                            const int*   __restrict__ iters_p,
                            const int*   __restrict__ cn_order,
                            float*       __restrict__ out)
{
    __shared__ float sh_vn[BPB * STRIDE];

    const int tid   = threadIdx.x;              // 0..63
    const int lane  = tid & 31;
    const int li    = lane & 7;                 // lane within 8-lane group
    const int sh    = lane & 24;                // group's bit offset in ballots
    const int g     = tid >> 3;                 // local batch 0..7
    const int batch = blockIdx.x * BPB + g;

    float* vn = sh_vn + g * STRIDE;

    // Load channel LLRs (float4 per lane; 8 lanes cover 32 floats per pass).
    const float4* src = (const float4*)(llr + (size_t)batch * NN);
    #pragma unroll 4
    for (int k = li; k < NN / 4; k += 8) {
        const float4 v = __ldg(src + k);
        vn[4*k + 0] = v.x;  vn[4*k + 1] = v.y;
        vn[4*k + 2] = v.z;  vn[4*k + 3] = v.w;
    }
    __syncwarp();

    const int iters = *iters_p;
    const int total = iters * MM;               // 2560, even

    // ---- 2-deep software pipeline ----
    int cnA, cnB, iloA, ihiA, iloB, ihiB;
    float cloA, chiA, cloB, chiB;
    int tm = 0;
    PREFETCH(A, 0);
    PREFETCH(B, 1);

    for (int t = 0; t < total; t += 2) {
        STEP(A); PREFETCH(A, t + 2);   // cn_{t+2} != cn_t: safe vs this step's store
        STEP(B); PREFETCH(B, t + 3);
    }

    // Hard decision output.
    float4* dst = (float4*)(out + (size_t)batch * NN);
    #pragma unroll 4
    for (int k = li; k < NN / 4; k += 8) {
        float4 r;
        r.x = (vn[4*k + 0] < 0.f) ? 1.f : 0.f;
        r.y = (vn[4*k + 1] < 0.f) ? 1.f : 0.f;
        r.z = (vn[4*k + 2] < 0.f) ? 1.f : 0.f;
        r.w = (vn[4*k + 3] < 0.f) ? 1.f : 0.f;
        dst[k] = r;
    }
}

extern "C" void kernel_launch(void* const* d_in, const int* in_sizes, int n_in,
                              void* d_out, int out_size)
{
    const float* llr      = (const float*)d_in[0];   // channel_llr [4096,1024] f32
    const int*   H        = (const int*)  d_in[1];   // H_compact   [512,16]    i32
    const int*   iters_p  = (const int*)  d_in[2];   // iters scalar
    const int*   cn_order = (const int*)  d_in[3];   // cn_order    [512]       i32
    float*       out      = (float*)d_out;

    (void)in_sizes; (void)n_in; (void)out_size;

    ldpc_layered_ms_kernel<<<BB / BPB, 64>>>(llr, H, iters_p, cn_order, out);
}